// round 4
// baseline (speedup 1.0000x reference)
#include <cuda_runtime.h>
#include <cuda_bf16.h>
#include <math.h>

#define BS_   64
#define NQ_   300
#define T_    1280            // 64 * 20 targets
#define ROWS_ (BS_ * NQ_)     // 19200
#define RPB_  13              // rows per block -> 1477 blocks = 1.996 * (148*5) slots
#define THREADS_ 320          // 1280 cols / 4 per thread

__device__ __forceinline__ float frcp(float x) {
    float r;
    asm("rcp.approx.f32 %0, %1;" : "=f"(r) : "f"(x));
    return r;
}

__global__ __launch_bounds__(THREADS_, 5)   // cap 40 regs -> 5 CTAs/SM -> 740 slots
void hungarian_cost_kernel(const float* __restrict__ logits,   // [ROWS_, 2]
                           const float* __restrict__ spans,    // [ROWS_, 2] (cx, w)
                           const float* __restrict__ tgt,      // [T_, 2]    (cx, w)
                           const float* __restrict__ refp,     // [ROWS_, 2]
                           float* __restrict__ out)            // [ROWS_, T_]
{
    // per-row constants packed as one float4: {cx, hw, unused->rc1 slots}
    // layout: {cx, hw, rc1, 0}
    __shared__ float4 s_row[RPB_];

    const int t    = threadIdx.x;          // owns columns 4t..4t+3
    const int row0 = blockIdx.x * RPB_;

    // ---- this thread's 4 target tuples: keep only tcx and th = 0.5*tw ----
    const float4 ta = __ldg(reinterpret_cast<const float4*>(tgt) + 2 * t);
    const float4 tb = __ldg(reinterpret_cast<const float4*>(tgt) + 2 * t + 1);

    float tcx[4], th[4];
    tcx[0] = ta.x; th[0] = 0.5f * ta.y;
    tcx[1] = ta.z; th[1] = 0.5f * ta.w;
    tcx[2] = tb.x; th[2] = 0.5f * tb.y;
    tcx[3] = tb.z; th[3] = 0.5f * tb.w;

    // ---- cooperative per-row constants (threads 0..RPB_-1) ----
    if (t < RPB_) {
        const int r = row0 + t;
        if (r < ROWS_) {
            const float l0 = __ldg(logits + 2 * r);
            const float l1 = __ldg(logits + 2 * r + 1);
            const float m  = fmaxf(l0, l1);
            const float e0 = __expf(l0 - m);
            const float e1 = __expf(l1 - m);
            const float p0 = __fdividef(e0, e0 + e1);  // softmax prob class 0

            const float cx = __ldg(spans + 2 * r);
            const float w  = __ldg(spans + 2 * r + 1);
            const float hw = 0.5f * w;
            const float x1 = cx - hw;
            const float x2 = cx + hw;

            const float r0 = __ldg(refp + 2 * r);
            const float r1 = __ldg(refp + 2 * r + 1);
            const float d0 = fabsf(x1 - r0);
            const float d1 = fabsf(x2 - r1);
            const float cref = sqrtf(fmaf(d0, d0, d1 * d1));

            // rc1 = cost_reference - class_prob + 1  (+1 from -giou fold)
            s_row[t] = make_float4(cx, hw, cref - p0 + 1.0f, 0.0f);
        }
    }
    __syncthreads();

    float4* op = reinterpret_cast<float4*>(out + (size_t)row0 * T_) + t;

    // ---- main loop: RPB_ rows, 4 columns each, one float4 store per row ----
#pragma unroll
    for (int rr = 0; rr < RPB_; ++rr) {
        const float4 rd  = s_row[rr];
        const float cx   = rd.x;
        const float hw   = rd.y;
        const float rc1  = rd.z;

        float v[4];
#pragma unroll
        for (int i = 0; i < 4; ++i) {
            const float d0 = cx - tcx[i];            // cx - tcx
            const float e1 = hw - th[i];             // 0.5*(w - tw)
            const float hs = hw + th[i];             // 0.5*(w + tw)
            // L1 span cost: |d0| + |2*e1|, plus folded row constant
            const float d1   = e1 + e1;
            const float base = (fabsf(d0) + fabsf(d1)) + rc1;
            // 1D GIoU via |u|+|v| = 2*max(|d0|,|e1|):
            //   ri  = min(x2,tx2)-max(x1,tx1) = hs - max(|d0|,|e1|)
            const float m     = fmaxf(fabsf(d0), fabsf(e1));
            const float ri    = hs - m;
            const float inter = fmaxf(ri, 0.0f);
            const float uni   = fmaf(2.0f, hs, -inter);   // s - inter (FFMA-imm)
            const float enc   = fmaf(2.0f, hs, -ri);      // s - ri
            const float ru    = frcp(uni);
            const float re    = frcp(enc);
            // v = base - inter/uni - uni/enc
            const float acc = fmaf(-inter, ru, base);
            v[i] = fmaf(-uni, re, acc);
        }

        if (row0 + rr < ROWS_) {
            *op = make_float4(v[0], v[1], v[2], v[3]);
        }
        op += T_ / 4;
    }
}

extern "C" void kernel_launch(void* const* d_in, const int* in_sizes, int n_in,
                              void* d_out, int out_size) {
    const float* logits = (const float*)d_in[0];  // pred_logits [64,300,2]
    const float* spans  = (const float*)d_in[1];  // pred_spans  [64,300,2]
    const float* tgt    = (const float*)d_in[2];  // tgt_spans   [1280,2]
    const float* refp   = (const float*)d_in[3];  // ref_points  [64,300,2]
    float* out = (float*)d_out;                   // [64,300,1280] fp32

    const int blocks = (ROWS_ + RPB_ - 1) / RPB_; // 1477
    hungarian_cost_kernel<<<blocks, THREADS_>>>(logits, spans, tgt, refp, out);
}